// round 3
// baseline (speedup 1.0000x reference)
#include <cuda_runtime.h>
#include <math.h>

#define NE   2048
#define CIN  512
#define DD   256
#define SCALE 0.04419417382415922f   /* 1/sqrt(2*256) */

// ---------------- scratch (static device globals; no allocation) ----------------
__device__ float g_wt1[3][4608 * 256];               // conv1 weights transposed [cin*9][cout]
__device__ float g_wt2[3][2304 * 256];               // conv2 weights transposed
__device__ float g_mid[(size_t)NE * DD * 36];        // conv1 output [N][256][6*6]
__device__ float g_qkv[3][(size_t)NE * DD * 16];     // conv2 outputs (flattened q/k/v)
__device__ int   g_stride;                           // 1 if gid is int32, 2 if int64(le)

// ---------------- graph-id dtype detection --------------------------------------
// int32 view of a sorted int64 array (values >=0, any value >0) is NOT sorted
// (pattern v,0,v',0,...). A sorted int32 view => genuine int32 data.
__global__ void k_detect(const int* __restrict__ gid32) {
    __shared__ int bad;
    if (threadIdx.x == 0) bad = 0;
    __syncthreads();
    for (int i = threadIdx.x; i < NE - 1; i += blockDim.x)
        if (gid32[i] > gid32[i + 1]) bad = 1;
    __syncthreads();
    if (threadIdx.x == 0) g_stride = bad ? 2 : 1;
}

// ---------------- weight transposes: w[cout][cin*9] -> wt[cin*9][cout] ----------
__global__ void k_transpose1(const float* __restrict__ w, int h) {
    int idx = blockIdx.x * 256 + threadIdx.x;        // grid = 4608 blocks exactly
    int c = idx & 255;
    int k = idx >> 8;
    g_wt1[h][idx] = w[c * 4608 + k];
}

__global__ void k_transpose2(const float* __restrict__ w, int h) {
    int idx = blockIdx.x * 256 + threadIdx.x;        // grid = 2304 blocks exactly
    int c = idx & 255;
    int k = idx >> 8;
    g_wt2[h][idx] = w[c * 2304 + k];
}

// ---------------- conv1: [N,512,8,8] -> relu -> [N,256,6,6] ---------------------
__global__ __launch_bounds__(256, 2)
void k_conv1(const float* __restrict__ x, const float* __restrict__ bias, int h) {
    __shared__ float sin_[128 * 64];                 // 128 cins x 8x8 = 32 KB
    const int n    = blockIdx.x;
    const int tid  = threadIdx.x;
    const int cout = tid;

    float acc[36];
#pragma unroll
    for (int p = 0; p < 36; ++p) acc[p] = 0.f;

    const float4* xg = (const float4*)(x + (size_t)n * CIN * 64);
    const float*  wt = g_wt1[h];

    for (int ch = 0; ch < 4; ++ch) {
        __syncthreads();
#pragma unroll
        for (int t = 0; t < 8; ++t) {
            int i4 = tid + t * 256;                  // 2048 float4 per chunk
            ((float4*)sin_)[i4] = xg[ch * 2048 + i4];
        }
        __syncthreads();

#pragma unroll 1
        for (int c = 0; c < 128; ++c) {
            const float* wp = wt + (size_t)((ch * 128 + c) * 9) * 256 + cout;
            float w0 = wp[0],      w1 = wp[256],    w2 = wp[512];
            float w3 = wp[768],    w4 = wp[1024],   w5 = wp[1280];
            float w6 = wp[1536],   w7 = wp[1792],   w8 = wp[2048];
            const float* sp = sin_ + c * 64;
#pragma unroll
            for (int oy = 0; oy < 6; ++oy) {
                float4 a0 = *(const float4*)(sp + oy * 8);
                float4 a1 = *(const float4*)(sp + oy * 8 + 4);
                float4 b0 = *(const float4*)(sp + oy * 8 + 8);
                float4 b1 = *(const float4*)(sp + oy * 8 + 12);
                float4 c0 = *(const float4*)(sp + oy * 8 + 16);
                float4 c1 = *(const float4*)(sp + oy * 8 + 20);
                float ra[8] = {a0.x, a0.y, a0.z, a0.w, a1.x, a1.y, a1.z, a1.w};
                float rb[8] = {b0.x, b0.y, b0.z, b0.w, b1.x, b1.y, b1.z, b1.w};
                float rc[8] = {c0.x, c0.y, c0.z, c0.w, c1.x, c1.y, c1.z, c1.w};
#pragma unroll
                for (int ox = 0; ox < 6; ++ox) {
                    float s = acc[oy * 6 + ox];
                    s = fmaf(ra[ox],     w0, s);
                    s = fmaf(ra[ox + 1], w1, s);
                    s = fmaf(ra[ox + 2], w2, s);
                    s = fmaf(rb[ox],     w3, s);
                    s = fmaf(rb[ox + 1], w4, s);
                    s = fmaf(rb[ox + 2], w5, s);
                    s = fmaf(rc[ox],     w6, s);
                    s = fmaf(rc[ox + 1], w7, s);
                    s = fmaf(rc[ox + 2], w8, s);
                    acc[oy * 6 + ox] = s;
                }
            }
        }
    }

    float b = bias[cout];
    float* yp = g_mid + (size_t)n * (DD * 36) + cout * 36;
#pragma unroll
    for (int p = 0; p < 36; ++p) yp[p] = fmaxf(acc[p] + b, 0.f);
}

// ---------------- conv2: [N,256,6,6] -> relu -> [N,256,4,4] ---------------------
__global__ __launch_bounds__(256, 2)
void k_conv2(const float* __restrict__ bias, int h) {
    __shared__ float sin_[128 * 48];                 // 128 cins x 6 rows x 8(pad)
    const int n    = blockIdx.x;
    const int tid  = threadIdx.x;
    const int cout = tid;

    float acc[16];
#pragma unroll
    for (int p = 0; p < 16; ++p) acc[p] = 0.f;

    const float* xin = g_mid + (size_t)n * (DD * 36);
    const float* wt  = g_wt2[h];

    for (int ch = 0; ch < 2; ++ch) {
        __syncthreads();
#pragma unroll
        for (int t = 0; t < 18; ++t) {
            int idx = tid + t * 256;                 // 0..4607
            int c   = idx / 36;
            int rem = idx - c * 36;
            int r   = rem / 6;
            int col = rem - r * 6;
            sin_[c * 48 + r * 8 + col] = xin[(ch * 128 + c) * 36 + rem];
        }
        __syncthreads();

#pragma unroll 1
        for (int c = 0; c < 128; ++c) {
            const float* wp = wt + (size_t)((ch * 128 + c) * 9) * 256 + cout;
            float w0 = wp[0],      w1 = wp[256],    w2 = wp[512];
            float w3 = wp[768],    w4 = wp[1024],   w5 = wp[1280];
            float w6 = wp[1536],   w7 = wp[1792],   w8 = wp[2048];
            const float* sp = sin_ + c * 48;
#pragma unroll
            for (int oy = 0; oy < 4; ++oy) {
                float4 a0 = *(const float4*)(sp + oy * 8);
                float4 a1 = *(const float4*)(sp + oy * 8 + 4);
                float4 b0 = *(const float4*)(sp + oy * 8 + 8);
                float4 b1 = *(const float4*)(sp + oy * 8 + 12);
                float4 c0 = *(const float4*)(sp + oy * 8 + 16);
                float4 c1 = *(const float4*)(sp + oy * 8 + 20);
                float ra[8] = {a0.x, a0.y, a0.z, a0.w, a1.x, a1.y, a1.z, a1.w};
                float rb[8] = {b0.x, b0.y, b0.z, b0.w, b1.x, b1.y, b1.z, b1.w};
                float rc[8] = {c0.x, c0.y, c0.z, c0.w, c1.x, c1.y, c1.z, c1.w};
#pragma unroll
                for (int ox = 0; ox < 4; ++ox) {
                    float s = acc[oy * 4 + ox];
                    s = fmaf(ra[ox],     w0, s);
                    s = fmaf(ra[ox + 1], w1, s);
                    s = fmaf(ra[ox + 2], w2, s);
                    s = fmaf(rb[ox],     w3, s);
                    s = fmaf(rb[ox + 1], w4, s);
                    s = fmaf(rb[ox + 2], w5, s);
                    s = fmaf(rc[ox],     w6, s);
                    s = fmaf(rc[ox + 1], w7, s);
                    s = fmaf(rc[ox + 2], w8, s);
                    acc[oy * 4 + ox] = s;
                }
            }
        }
    }

    float b = bias[cout];
    float* yp = g_qkv[h] + (size_t)n * (DD * 16) + cout * 16;
#pragma unroll
    for (int p = 0; p < 16; ++p) yp[p] = fmaxf(acc[p] + b, 0.f);
}

// ---------------- fused block-diagonal attention --------------------------------
__global__ __launch_bounds__(256)
void k_attn(const int* __restrict__ gid32, float* __restrict__ out) {
    __shared__ float qs[4096];                       // 16 KB: q row
    __shared__ float srow[2048];                     // 8 KB: score row (worst case)
    __shared__ float red[8];

    const int i    = blockIdx.x;
    const int tid  = threadIdx.x;
    const int warp = tid >> 5;
    const int lane = tid & 31;
    const int st   = g_stride;                       // 1: int32 ids, 2: int64 low words

    const int g = gid32[i * st];
    int rs, re;
    {   // lower bound
        int a = 0, b = NE;
        while (a < b) { int m = (a + b) >> 1; if (gid32[m * st] < g) a = m + 1; else b = m; }
        rs = a;
    }
    {   // upper bound
        int a = 0, b = NE;
        while (a < b) { int m = (a + b) >> 1; if (gid32[m * st] <= g) a = m + 1; else b = m; }
        re = a;
    }

    const float* qf = g_qkv[0];
    const float* kf = g_qkv[1];
    const float* vf = g_qkv[2];

    // load q_i into smem
    const float4* qg = (const float4*)(qf + (size_t)i * 4096);
#pragma unroll
    for (int t = 0; t < 4; ++t) ((float4*)qs)[tid + t * 256] = qg[tid + t * 256];
    __syncthreads();

    // scores: one j per warp
    for (int j = rs + warp; j < re; j += 8) {
        const float4* kp = (const float4*)(kf + (size_t)j * 4096);
        const float4* qp = (const float4*)qs;
        float s = 0.f;
#pragma unroll 4
        for (int t = lane; t < 1024; t += 32) {
            float4 kv = kp[t];
            float4 qv = qp[t];
            s = fmaf(kv.x, qv.x, s);
            s = fmaf(kv.y, qv.y, s);
            s = fmaf(kv.z, qv.z, s);
            s = fmaf(kv.w, qv.w, s);
        }
#pragma unroll
        for (int o = 16; o; o >>= 1) s += __shfl_xor_sync(0xffffffffu, s, o);
        if (lane == 0) srow[j - rs] = s * SCALE;
    }
    __syncthreads();

    const int len = re - rs;

    // softmax: max
    float m = -INFINITY;
    for (int t = tid; t < len; t += 256) m = fmaxf(m, srow[t]);
#pragma unroll
    for (int o = 16; o; o >>= 1) m = fmaxf(m, __shfl_xor_sync(0xffffffffu, m, o));
    if (lane == 0) red[warp] = m;
    __syncthreads();
    float mm = red[0];
#pragma unroll
    for (int w = 1; w < 8; ++w) mm = fmaxf(mm, red[w]);
    __syncthreads();

    // exp + sum
    float ssum = 0.f;
    for (int t = tid; t < len; t += 256) {
        float e = __expf(srow[t] - mm);
        srow[t] = e;
        ssum += e;
    }
#pragma unroll
    for (int o = 16; o; o >>= 1) ssum += __shfl_xor_sync(0xffffffffu, ssum, o);
    if (lane == 0) red[warp] = ssum;
    __syncthreads();
    float tot = red[0];
#pragma unroll
    for (int w = 1; w < 8; ++w) tot += red[w];
    const float inv = 1.f / tot;

    // out_i = sum_j p_ij * v_j ; each thread owns 16 output features (4 float4)
    float4 a0 = make_float4(0.f, 0.f, 0.f, 0.f);
    float4 a1 = a0, a2 = a0, a3 = a0;
#pragma unroll 2
    for (int j = rs; j < re; ++j) {
        float a = srow[j - rs] * inv;
        const float4* vp = (const float4*)(vf + (size_t)j * 4096);
        float4 v0 = vp[tid];
        float4 v1 = vp[tid + 256];
        float4 v2 = vp[tid + 512];
        float4 v3 = vp[tid + 768];
        a0.x = fmaf(a, v0.x, a0.x); a0.y = fmaf(a, v0.y, a0.y);
        a0.z = fmaf(a, v0.z, a0.z); a0.w = fmaf(a, v0.w, a0.w);
        a1.x = fmaf(a, v1.x, a1.x); a1.y = fmaf(a, v1.y, a1.y);
        a1.z = fmaf(a, v1.z, a1.z); a1.w = fmaf(a, v1.w, a1.w);
        a2.x = fmaf(a, v2.x, a2.x); a2.y = fmaf(a, v2.y, a2.y);
        a2.z = fmaf(a, v2.z, a2.z); a2.w = fmaf(a, v2.w, a2.w);
        a3.x = fmaf(a, v3.x, a3.x); a3.y = fmaf(a, v3.y, a3.y);
        a3.z = fmaf(a, v3.z, a3.z); a3.w = fmaf(a, v3.w, a3.w);
    }
    float4* op = (float4*)(out + (size_t)i * 4096);
    op[tid]       = a0;
    op[tid + 256] = a1;
    op[tid + 512] = a2;
    op[tid + 768] = a3;
}

// ---------------- launch --------------------------------------------------------
extern "C" void kernel_launch(void* const* d_in, const int* in_sizes, int n_in,
                              void* d_out, int out_size) {
    const float* x     = (const float*)d_in[0];
    const int*   gid32 = (const int*)d_in[1];

    const float* w1[3] = {(const float*)d_in[2],  (const float*)d_in[6],  (const float*)d_in[10]};
    const float* b1[3] = {(const float*)d_in[3],  (const float*)d_in[7],  (const float*)d_in[11]};
    const float* w2[3] = {(const float*)d_in[4],  (const float*)d_in[8],  (const float*)d_in[12]};
    const float* b2[3] = {(const float*)d_in[5],  (const float*)d_in[9],  (const float*)d_in[13]};

    k_detect<<<1, 256>>>(gid32);
    for (int h = 0; h < 3; ++h) {
        k_transpose1<<<4608, 256>>>(w1[h], h);
        k_transpose2<<<2304, 256>>>(w2[h], h);
    }
    for (int h = 0; h < 3; ++h) {
        k_conv1<<<NE, 256>>>(x, b1[h], h);
        k_conv2<<<NE, 256>>>(b2[h], h);
    }
    k_attn<<<NE, 256>>>(gid32, (float*)d_out);
}

// round 5
// speedup vs baseline: 2.4190x; 2.4190x over previous
#include <cuda_runtime.h>
#include <cuda_bf16.h>
#include <math.h>
#include <stdint.h>

#define NE 2048
#define SCALE 0.04419417382415922f   /* 1/sqrt(2*256) */

// ---------------- device scratch (static globals; no allocation) ----------------
__device__ __align__(16) __nv_bfloat16 g_xh[(size_t)NE * 64 * 512];   // x NHWC bf16 hi
__device__ __align__(16) __nv_bfloat16 g_xl[(size_t)NE * 64 * 512];   // x NHWC bf16 lo
__device__ __align__(16) __nv_bfloat16 g_w1h[3][4608 * 256];          // conv1 W [cout][k] hi
__device__ __align__(16) __nv_bfloat16 g_w1l[3][4608 * 256];
__device__ __align__(16) __nv_bfloat16 g_w2h[3][2304 * 256];          // conv2 W
__device__ __align__(16) __nv_bfloat16 g_w2l[3][2304 * 256];
__device__ __align__(16) __nv_bfloat16 g_m1h[3][(size_t)73728 * 256]; // conv1 out [m][cout]
__device__ __align__(16) __nv_bfloat16 g_m1l[3][(size_t)73728 * 256];
__device__ float g_qkv[3][(size_t)NE * 4096];                          // conv2 out fp32
__device__ int   g_stride;

// ---------------- PTX helpers (plain compute_103-legal only) ----------------------
__device__ __forceinline__ uint32_t smem_u32(const void* p) {
    uint32_t a;
    asm("{ .reg .u64 t; cvta.to.shared.u64 t, %1; cvt.u32.u64 %0, t; }" : "=r"(a) : "l"(p));
    return a;
}
__device__ __forceinline__ void cpa16(uint32_t dst, const void* src) {
    asm volatile("cp.async.cg.shared.global [%0], [%1], 16;" :: "r"(dst), "l"(src) : "memory");
}
#define CP_COMMIT() asm volatile("cp.async.commit_group;" ::: "memory")
#define CP_WAIT1()  asm volatile("cp.async.wait_group 1;" ::: "memory")
#define CP_WAIT0()  asm volatile("cp.async.wait_group 0;" ::: "memory")

__device__ __forceinline__ void ldm4(uint32_t* r, uint32_t addr) {
    asm volatile("ldmatrix.sync.aligned.m8n8.x4.shared.b16 {%0,%1,%2,%3}, [%4];"
        : "=r"(r[0]), "=r"(r[1]), "=r"(r[2]), "=r"(r[3]) : "r"(addr));
}
__device__ __forceinline__ void mma16816(float* d, const uint32_t* a, uint32_t b0, uint32_t b1) {
    asm volatile("mma.sync.aligned.m16n8k16.row.col.f32.bf16.bf16.f32 "
        "{%0,%1,%2,%3}, {%4,%5,%6,%7}, {%8,%9}, {%0,%1,%2,%3};"
        : "+f"(d[0]), "+f"(d[1]), "+f"(d[2]), "+f"(d[3])
        : "r"(a[0]), "r"(a[1]), "r"(a[2]), "r"(a[3]), "r"(b0), "r"(b1));
}

// ---------------- graph-id dtype detection ---------------------------------------
__global__ void k_detect(const int* __restrict__ gid32) {
    __shared__ int bad;
    if (threadIdx.x == 0) bad = 0;
    __syncthreads();
    for (int i = threadIdx.x; i < NE - 1; i += blockDim.x)
        if (gid32[i] > gid32[i + 1]) bad = 1;
    __syncthreads();
    if (threadIdx.x == 0) g_stride = bad ? 2 : 1;
}

// ---------------- prep: x NCHW fp32 -> NHWC bf16 hi/lo ----------------------------
__global__ void k_prep_x(const float* __restrict__ x) {      // grid (2048, 8), 256 thr
    __shared__ float tile[64][65];
    const int n = blockIdx.x, cc = blockIdx.y;
#pragma unroll
    for (int i = 0; i < 16; ++i) {
        int t = threadIdx.x + i * 256;
        int ci = t >> 6, yx = t & 63;
        tile[ci][yx] = x[(size_t)n * 32768 + (cc * 64 + ci) * 64 + yx];
    }
    __syncthreads();
#pragma unroll
    for (int i = 0; i < 16; ++i) {
        int t = threadIdx.x + i * 256;
        int yx = t >> 6, ci = t & 63;
        float v = tile[ci][yx];
        __nv_bfloat16 h = __float2bfloat16(v);
        __nv_bfloat16 l = __float2bfloat16(v - __bfloat162float(h));
        size_t o = ((size_t)n * 64 + yx) * 512 + cc * 64 + ci;
        g_xh[o] = h; g_xl[o] = l;
    }
}

// ---------------- prep: weights -> [cout][kpos*Cin + cin] bf16 hi/lo --------------
__global__ void k_prep_w1(const float* __restrict__ wq, const float* __restrict__ wk,
                          const float* __restrict__ wv) {    // grid (256, 3)
    const int cout = blockIdx.x, h = blockIdx.y;
    const float* w = (h == 0) ? wq : (h == 1) ? wk : wv;
#pragma unroll
    for (int i = 0; i < 18; ++i) {
        int k = threadIdx.x + i * 256;                       // 0..4607
        int kpos = k >> 9, cin = k & 511;
        float v = w[cout * 4608 + cin * 9 + kpos];
        __nv_bfloat16 hh = __float2bfloat16(v);
        __nv_bfloat16 ll = __float2bfloat16(v - __bfloat162float(hh));
        g_w1h[h][cout * 4608 + k] = hh;
        g_w1l[h][cout * 4608 + k] = ll;
    }
}

__global__ void k_prep_w2(const float* __restrict__ wq, const float* __restrict__ wk,
                          const float* __restrict__ wv) {    // grid (256, 3)
    const int cout = blockIdx.x, h = blockIdx.y;
    const float* w = (h == 0) ? wq : (h == 1) ? wk : wv;
#pragma unroll
    for (int i = 0; i < 9; ++i) {
        int k = threadIdx.x + i * 256;                       // 0..2303
        int kpos = k >> 8, cin = k & 255;
        float v = w[cout * 2304 + cin * 9 + kpos];
        __nv_bfloat16 hh = __float2bfloat16(v);
        __nv_bfloat16 ll = __float2bfloat16(v - __bfloat162float(hh));
        g_w2h[h][cout * 2304 + k] = hh;
        g_w2l[h][cout * 2304 + k] = ll;
    }
}

// ---------------- HMMA GEMM: conv1 (PHASE 1) / conv2 (PHASE 2) --------------------
// CTA: M=128 x N=256, K chunks of 64. 8 warps, each 64x64. 2-stage cp.async pipe.
// Stage layout: Ah @0 (16K) | Al @16K | Bh @32K (32K) | Bl @64K (32K) = 96K.
#define STAGE_BYTES 98304
#define SMEM_DYN    (2 * STAGE_BYTES)
#define EPI_PITCH   260

template <int PHASE>
__global__ void __launch_bounds__(256, 1)
k_gemm(const float* __restrict__ bq, const float* __restrict__ bk,
       const float* __restrict__ bv) {
    extern __shared__ __align__(1024) char dsm[];
    const uint32_t sbase = smem_u32(dsm);

    const int tile = blockIdx.x, head = blockIdx.y;
    const int tid  = threadIdx.x, wid = tid >> 5, lane = tid & 31;
    const int wm   = (wid >> 2) * 64;        // warp m offset
    const int wn   = (wid & 3) * 64;         // warp n offset
    const float* bias = (head == 0) ? bq : (head == 1) ? bk : bv;

    __shared__ int s_basix[128];

    constexpr int CHUNKS = (PHASE == 1) ? 72 : 36;
    constexpr int CPK    = (PHASE == 1) ? 8 : 4;
    constexpr int KCIN   = (PHASE == 1) ? 512 : 256;
    constexpr int KTOT   = (PHASE == 1) ? 4608 : 2304;

    if (tid < 128) {
        int m = tile * 128 + tid;
        if (PHASE == 1) {
            int n = m / 36, p = m - n * 36, oy = p / 6, ox = p - oy * 6;
            s_basix[tid] = (n * 64 + oy * 8 + ox) * 512;
        } else {
            int n = m >> 4, p = m & 15, oy = p >> 2, ox = p & 3;
            s_basix[tid] = (n * 36 + oy * 6 + ox) * 256;
        }
    }
    __syncthreads();

    const __nv_bfloat16 *Ah, *Al, *Bh, *Bl;
    if (PHASE == 1) { Ah = g_xh;        Al = g_xl;        Bh = g_w1h[head]; Bl = g_w1l[head]; }
    else            { Ah = g_m1h[head]; Al = g_m1l[head]; Bh = g_w2h[head]; Bl = g_w2l[head]; }

    // ---- prefetch lambda: gather chunk c into stage (c&1) ----
    auto prefetch = [&](int c) {
        const int kpos = c / CPK;
        const int coff = (c - kpos * CPK) * 64;
        const int ky = kpos / 3, kx = kpos - ky * 3;
        const int kadd = (PHASE == 1) ? ((ky * 8 + kx) * 512 + coff)
                                      : ((ky * 6 + kx) * 256 + coff);
        const int bko = kpos * KCIN + coff;
        const uint32_t stg = sbase + (c & 1) * STAGE_BYTES;
#pragma unroll
        for (int i = 0; i < 4; ++i) {                      // A: 128 rows x 128B
            int idx = tid + i * 256;
            int r = idx >> 3, seg = idx & 7;
            size_t e = (size_t)s_basix[r] + kadd + seg * 8;
            uint32_t off = (uint32_t)(r * 128 + seg * 16);
            uint32_t sw = off ^ ((uint32_t)(r & 7) << 4);
            cpa16(stg + sw,         Ah + e);
            cpa16(stg + 16384 + sw, Al + e);
        }
#pragma unroll
        for (int i = 0; i < 8; ++i) {                      // B: 256 rows x 128B
            int idx = tid + i * 256;
            int r = idx >> 3, seg = idx & 7;
            size_t e = (size_t)r * KTOT + bko + seg * 8;
            uint32_t off = (uint32_t)(r * 128 + seg * 16);
            uint32_t sw = off ^ ((uint32_t)(r & 7) << 4);
            cpa16(stg + 32768 + sw, Bh + e);
            cpa16(stg + 65536 + sw, Bl + e);
        }
        CP_COMMIT();
    };

    float acc[4][8][4];
#pragma unroll
    for (int mt = 0; mt < 4; ++mt)
#pragma unroll
        for (int nt = 0; nt < 8; ++nt)
#pragma unroll
            for (int q = 0; q < 4; ++q) acc[mt][nt][q] = 0.f;

    prefetch(0);
    prefetch(1);

    const uint32_t lrow = lane & 15;
    const uint32_t lhi  = (uint32_t)(lane >> 4) << 4;

#pragma unroll 1
    for (int c = 0; c < CHUNKS; ++c) {
        if (c + 1 < CHUNKS) CP_WAIT1(); else CP_WAIT0();
        __syncthreads();
        const uint32_t stg = sbase + (c & 1) * STAGE_BYTES;

#pragma unroll
        for (int ks = 0; ks < 4; ++ks) {
            uint32_t ah[4][4], bh[4][4], bl[4][4], al[4][4];
            // A hi
#pragma unroll
            for (int mt = 0; mt < 4; ++mt) {
                uint32_t row = (uint32_t)(wm + mt * 16) + lrow;
                uint32_t off = row * 128 + (uint32_t)ks * 32 + lhi;
                ldm4(ah[mt], stg + (off ^ ((row & 7) << 4)));
            }
            // B hi
#pragma unroll
            for (int nt2 = 0; nt2 < 4; ++nt2) {
                uint32_t row = (uint32_t)(wn + nt2 * 16) + lrow;
                uint32_t off = row * 128 + (uint32_t)ks * 32 + lhi;
                ldm4(bh[nt2], stg + 32768 + (off ^ ((row & 7) << 4)));
            }
            // pass 1: Ah * Bh
#pragma unroll
            for (int mt = 0; mt < 4; ++mt)
#pragma unroll
                for (int nt = 0; nt < 8; ++nt)
                    mma16816(acc[mt][nt], ah[mt], bh[nt >> 1][nt & 1], bh[nt >> 1][(nt & 1) + 2]);
            // B lo
#pragma unroll
            for (int nt2 = 0; nt2 < 4; ++nt2) {
                uint32_t row = (uint32_t)(wn + nt2 * 16) + lrow;
                uint32_t off = row * 128 + (uint32_t)ks * 32 + lhi;
                ldm4(bl[nt2], stg + 65536 + (off ^ ((row & 7) << 4)));
            }
            // pass 2: Ah * Bl
#pragma unroll
            for (int mt = 0; mt < 4; ++mt)
#pragma unroll
                for (int nt = 0; nt < 8; ++nt)
                    mma16816(acc[mt][nt], ah[mt], bl[nt >> 1][nt & 1], bl[nt >> 1][(nt & 1) + 2]);
            // A lo
#pragma unroll
            for (int mt = 0; mt < 4; ++mt) {
                uint32_t row = (uint32_t)(wm + mt * 16) + lrow;
                uint32_t off = row * 128 + (uint32_t)ks * 32 + lhi;
                ldm4(al[mt], stg + 16384 + (off ^ ((row & 7) << 4)));
            }
            // pass 3: Al * Bh
#pragma unroll
            for (int mt = 0; mt < 4; ++mt)
#pragma unroll
                for (int nt = 0; nt < 8; ++nt)
                    mma16816(acc[mt][nt], al[mt], bh[nt >> 1][nt & 1], bh[nt >> 1][(nt & 1) + 2]);
        }

        __syncthreads();
        if (c + 2 < CHUNKS) prefetch(c + 2);
    }

    // ---- epilogue: frags -> smem -> (bias, relu) -> global ----
    float* epi = (float*)dsm;
    __syncthreads();
#pragma unroll
    for (int mt = 0; mt < 4; ++mt)
#pragma unroll
        for (int nt = 0; nt < 8; ++nt) {
            int r0 = wm + mt * 16 + (lane >> 2);
            int c0 = wn + nt * 8 + (lane & 3) * 2;
            *(float2*)&epi[r0 * EPI_PITCH + c0]       = make_float2(acc[mt][nt][0], acc[mt][nt][1]);
            *(float2*)&epi[(r0 + 8) * EPI_PITCH + c0] = make_float2(acc[mt][nt][2], acc[mt][nt][3]);
        }
    __syncthreads();

    if (PHASE == 1) {
        size_t mb = (size_t)tile * 128;
        const float b = bias[tid];
#pragma unroll 1
        for (int i = 0; i < 128; ++i) {
            float v = fmaxf(epi[i * EPI_PITCH + tid] + b, 0.f);
            __nv_bfloat16 h = __float2bfloat16(v);
            __nv_bfloat16 l = __float2bfloat16(v - __bfloat162float(h));
            size_t o = (mb + i) * 256 + tid;
            g_m1h[head][o] = h;
            g_m1l[head][o] = l;
        }
    } else {
        float* outp = g_qkv[head] + (size_t)tile * 8 * 4096;
#pragma unroll 1
        for (int i = 0; i < 128; ++i) {
            int idx = tid + i * 256;
            int nl = idx >> 12, f = idx & 4095;
            int cout = f >> 4, p = f & 15;
            outp[idx] = fmaxf(epi[(nl * 16 + p) * EPI_PITCH + cout] + bias[cout], 0.f);
        }
    }
}

// ---------------- fused block-diagonal attention ----------------------------------
__global__ __launch_bounds__(256)
void k_attn(const int* __restrict__ gid32, float* __restrict__ out) {
    __shared__ float qs[4096];
    __shared__ float srow[2048];
    __shared__ float red[8];

    const int i = blockIdx.x, tid = threadIdx.x;
    const int warp = tid >> 5, lane = tid & 31;
    const int st = g_stride;

    const int g = gid32[i * st];
    int rs, re;
    { int a = 0, b = NE;
      while (a < b) { int m = (a + b) >> 1; if (gid32[m * st] < g) a = m + 1; else b = m; }
      rs = a; }
    { int a = 0, b = NE;
      while (a < b) { int m = (a + b) >> 1; if (gid32[m * st] <= g) a = m + 1; else b = m; }
      re = a; }

    const float* qf = g_qkv[0];
    const float* kf = g_qkv[1];
    const float* vf = g_qkv[2];

    const float4* qg = (const float4*)(qf + (size_t)i * 4096);
#pragma unroll
    for (int t = 0; t < 4; ++t) ((float4*)qs)[tid + t * 256] = qg[tid + t * 256];
    __syncthreads();

    for (int j = rs + warp; j < re; j += 8) {
        const float4* kp = (const float4*)(kf + (size_t)j * 4096);
        const float4* qp = (const float4*)qs;
        float s = 0.f;
#pragma unroll 4
        for (int t = lane; t < 1024; t += 32) {
            float4 kv = kp[t], qv = qp[t];
            s = fmaf(kv.x, qv.x, s); s = fmaf(kv.y, qv.y, s);
            s = fmaf(kv.z, qv.z, s); s = fmaf(kv.w, qv.w, s);
        }
#pragma unroll
        for (int o = 16; o; o >>= 1) s += __shfl_xor_sync(0xffffffffu, s, o);
        if (lane == 0) srow[j - rs] = s * SCALE;
    }
    __syncthreads();

    const int len = re - rs;

    float m = -INFINITY;
    for (int t = tid; t < len; t += 256) m = fmaxf(m, srow[t]);
#pragma unroll
    for (int o = 16; o; o >>= 1) m = fmaxf(m, __shfl_xor_sync(0xffffffffu, m, o));
    if (lane == 0) red[warp] = m;
    __syncthreads();
    float mm = red[0];
#pragma unroll
    for (int w = 1; w < 8; ++w) mm = fmaxf(mm, red[w]);
    __syncthreads();

    float ssum = 0.f;
    for (int t = tid; t < len; t += 256) {
        float e = __expf(srow[t] - mm);
        srow[t] = e;
        ssum += e;
    }
#pragma unroll
    for (int o = 16; o; o >>= 1) ssum += __shfl_xor_sync(0xffffffffu, ssum, o);
    if (lane == 0) red[warp] = ssum;
    __syncthreads();
    float tot = red[0];
#pragma unroll
    for (int w = 1; w < 8; ++w) tot += red[w];
    const float inv = 1.f / tot;

    float4 a0 = make_float4(0.f, 0.f, 0.f, 0.f);
    float4 a1 = a0, a2 = a0, a3 = a0;
#pragma unroll 2
    for (int j = rs; j < re; ++j) {
        float a = srow[j - rs] * inv;
        const float4* vp = (const float4*)(vf + (size_t)j * 4096);
        float4 v0 = vp[tid], v1 = vp[tid + 256], v2 = vp[tid + 512], v3 = vp[tid + 768];
        a0.x = fmaf(a, v0.x, a0.x); a0.y = fmaf(a, v0.y, a0.y);
        a0.z = fmaf(a, v0.z, a0.z); a0.w = fmaf(a, v0.w, a0.w);
        a1.x = fmaf(a, v1.x, a1.x); a1.y = fmaf(a, v1.y, a1.y);
        a1.z = fmaf(a, v1.z, a1.z); a1.w = fmaf(a, v1.w, a1.w);
        a2.x = fmaf(a, v2.x, a2.x); a2.y = fmaf(a, v2.y, a2.y);
        a2.z = fmaf(a, v2.z, a2.z); a2.w = fmaf(a, v2.w, a2.w);
        a3.x = fmaf(a, v3.x, a3.x); a3.y = fmaf(a, v3.y, a3.y);
        a3.z = fmaf(a, v3.z, a3.z); a3.w = fmaf(a, v3.w, a3.w);
    }
    float4* op = (float4*)(out + (size_t)i * 4096);
    op[tid] = a0; op[tid + 256] = a1; op[tid + 512] = a2; op[tid + 768] = a3;
}

// ---------------- launch ----------------------------------------------------------
extern "C" void kernel_launch(void* const* d_in, const int* in_sizes, int n_in,
                              void* d_out, int out_size) {
    const float* x     = (const float*)d_in[0];
    const int*   gid32 = (const int*)d_in[1];

    const float* w1[3] = {(const float*)d_in[2], (const float*)d_in[6],  (const float*)d_in[10]};
    const float* b1[3] = {(const float*)d_in[3], (const float*)d_in[7],  (const float*)d_in[11]};
    const float* w2[3] = {(const float*)d_in[4], (const float*)d_in[8],  (const float*)d_in[12]};
    const float* b2[3] = {(const float*)d_in[5], (const float*)d_in[9],  (const float*)d_in[13]};

    cudaFuncSetAttribute(k_gemm<1>, cudaFuncAttributeMaxDynamicSharedMemorySize, SMEM_DYN);
    cudaFuncSetAttribute(k_gemm<2>, cudaFuncAttributeMaxDynamicSharedMemorySize, SMEM_DYN);

    k_detect<<<1, 256>>>(gid32);
    k_prep_x<<<dim3(2048, 8), 256>>>(x);
    k_prep_w1<<<dim3(256, 3), 256>>>(w1[0], w1[1], w1[2]);
    k_prep_w2<<<dim3(256, 3), 256>>>(w2[0], w2[1], w2[2]);

    k_gemm<1><<<dim3(576, 3), 256, SMEM_DYN>>>(b1[0], b1[1], b1[2]);
    k_gemm<2><<<dim3(256, 3), 256, SMEM_DYN>>>(b2[0], b2[1], b2[2]);

    k_attn<<<NE, 256>>>(gid32, (float*)d_out);
}

// round 7
// speedup vs baseline: 3.4106x; 1.4099x over previous
#include <cuda_runtime.h>
#include <cuda_fp16.h>
#include <math.h>
#include <stdint.h>

#define NE 2048
#define SCALE 0.04419417382415922f   /* 1/sqrt(2*256) */

// ---------------- device scratch (static globals; no allocation) ----------------
__device__ __align__(16) __half g_xh[(size_t)NE * 64 * 512];   // x NHWC fp16 hi
__device__ __align__(16) __half g_xl[(size_t)NE * 64 * 512];   // x NHWC fp16 lo
__device__ __align__(16) __half g_w1[3][4608 * 256];           // conv1 W [cout][k] fp16
__device__ __align__(16) __half g_w2[3][2304 * 256];           // conv2 W fp16
__device__ __align__(16) __half g_m1h[3][(size_t)73728 * 256]; // conv1 out hi
__device__ __align__(16) __half g_m1l[3][(size_t)73728 * 256]; // conv1 out lo
__device__ float g_qkv[3][(size_t)NE * 4096];                  // conv2 out fp32
__device__ int   g_stride;

// ---------------- PTX helpers -----------------------------------------------------
__device__ __forceinline__ uint32_t smem_u32(const void* p) {
    uint32_t a;
    asm("{ .reg .u64 t; cvta.to.shared.u64 t, %1; cvt.u32.u64 %0, t; }" : "=r"(a) : "l"(p));
    return a;
}
__device__ __forceinline__ void cpa16(uint32_t dst, const void* src) {
    asm volatile("cp.async.cg.shared.global [%0], [%1], 16;" :: "r"(dst), "l"(src) : "memory");
}
#define CP_COMMIT() asm volatile("cp.async.commit_group;" ::: "memory")
#define CP_WAIT2()  asm volatile("cp.async.wait_group 2;" ::: "memory")
#define CP_WAIT1()  asm volatile("cp.async.wait_group 1;" ::: "memory")
#define CP_WAIT0()  asm volatile("cp.async.wait_group 0;" ::: "memory")

__device__ __forceinline__ void ldm4(uint32_t* r, uint32_t addr) {
    asm volatile("ldmatrix.sync.aligned.m8n8.x4.shared.b16 {%0,%1,%2,%3}, [%4];"
        : "=r"(r[0]), "=r"(r[1]), "=r"(r[2]), "=r"(r[3]) : "r"(addr));
}
__device__ __forceinline__ void mma16816(float* d, const uint32_t* a, uint32_t b0, uint32_t b1) {
    asm volatile("mma.sync.aligned.m16n8k16.row.col.f32.f16.f16.f32 "
        "{%0,%1,%2,%3}, {%4,%5,%6,%7}, {%8,%9}, {%0,%1,%2,%3};"
        : "+f"(d[0]), "+f"(d[1]), "+f"(d[2]), "+f"(d[3])
        : "r"(a[0]), "r"(a[1]), "r"(a[2]), "r"(a[3]), "r"(b0), "r"(b1));
}

// ---------------- graph-id dtype detection ---------------------------------------
__global__ void k_detect(const int* __restrict__ gid32) {
    __shared__ int bad;
    if (threadIdx.x == 0) bad = 0;
    __syncthreads();
    for (int i = threadIdx.x; i < NE - 1; i += blockDim.x)
        if (gid32[i] > gid32[i + 1]) bad = 1;
    __syncthreads();
    if (threadIdx.x == 0) g_stride = bad ? 2 : 1;
}

// ---------------- prep: x NCHW fp32 -> NHWC fp16 hi/lo ----------------------------
__global__ void k_prep_x(const float* __restrict__ x) {      // grid (2048, 8), 256 thr
    __shared__ float tile[64][65];
    const int n = blockIdx.x, cc = blockIdx.y;
#pragma unroll
    for (int i = 0; i < 16; ++i) {
        int t = threadIdx.x + i * 256;
        int ci = t >> 6, yx = t & 63;
        tile[ci][yx] = x[(size_t)n * 32768 + (cc * 64 + ci) * 64 + yx];
    }
    __syncthreads();
#pragma unroll
    for (int i = 0; i < 16; ++i) {
        int t = threadIdx.x + i * 256;
        int yx = t >> 6, ci = t & 63;
        float v = tile[ci][yx];
        __half h = __float2half_rn(v);
        __half l = __float2half_rn(v - __half2float(h));
        size_t o = ((size_t)n * 64 + yx) * 512 + cc * 64 + ci;
        g_xh[o] = h; g_xl[o] = l;
    }
}

// ---------------- prep: weights -> [cout][kpos*Cin + cin] fp16 (hi only) ----------
__global__ void k_prep_w1(const float* __restrict__ wq, const float* __restrict__ wk,
                          const float* __restrict__ wv) {    // grid (256, 3)
    const int cout = blockIdx.x, h = blockIdx.y;
    const float* w = (h == 0) ? wq : (h == 1) ? wk : wv;
#pragma unroll
    for (int i = 0; i < 18; ++i) {
        int k = threadIdx.x + i * 256;                       // 0..4607
        int kpos = k >> 9, cin = k & 511;
        g_w1[h][cout * 4608 + k] = __float2half_rn(w[cout * 4608 + cin * 9 + kpos]);
    }
}

__global__ void k_prep_w2(const float* __restrict__ wq, const float* __restrict__ wk,
                          const float* __restrict__ wv) {    // grid (256, 3)
    const int cout = blockIdx.x, h = blockIdx.y;
    const float* w = (h == 0) ? wq : (h == 1) ? wk : wv;
#pragma unroll
    for (int i = 0; i < 9; ++i) {
        int k = threadIdx.x + i * 256;                       // 0..2303
        int kpos = k >> 8, cin = k & 255;
        g_w2[h][cout * 2304 + k] = __float2half_rn(w[cout * 2304 + cin * 9 + kpos]);
    }
}

// ---------------- HMMA GEMM: conv1 (PHASE 1) / conv2 (PHASE 2) --------------------
// CTA: M=128 x N=256, K chunks of 64. 8 warps of 64x64. 3-stage cp.async pipeline.
// Stage: Ah @0 (16K) | Al @16K (16K) | B @32K (32K) = 64K. Passes: Ah*B + Al*B.
#define STAGE_BYTES 65536
#define SMEM_DYN    (3 * STAGE_BYTES)
#define EPI_PITCH   260

template <int PHASE>
__global__ void __launch_bounds__(256, 1)
k_gemm(const float* __restrict__ bq, const float* __restrict__ bk,
       const float* __restrict__ bv) {
    extern __shared__ __align__(1024) char dsm[];
    const uint32_t sbase = smem_u32(dsm);

    const int tile = blockIdx.x, head = blockIdx.y;
    const int tid  = threadIdx.x, wid = tid >> 5, lane = tid & 31;
    const int wm   = (wid >> 2) * 64;        // warp m offset
    const int wn   = (wid & 3) * 64;         // warp n offset
    const float* bias = (head == 0) ? bq : (head == 1) ? bk : bv;

    __shared__ int s_basix[128];

    constexpr int CHUNKS = (PHASE == 1) ? 72 : 36;
    constexpr int CPK    = (PHASE == 1) ? 8 : 4;
    constexpr int KCIN   = (PHASE == 1) ? 512 : 256;
    constexpr int KTOT   = (PHASE == 1) ? 4608 : 2304;

    if (tid < 128) {
        int m = tile * 128 + tid;
        if (PHASE == 1) {
            int n = m / 36, p = m - n * 36, oy = p / 6, ox = p - oy * 6;
            s_basix[tid] = (n * 64 + oy * 8 + ox) * 512;
        } else {
            int n = m >> 4, p = m & 15, oy = p >> 2, ox = p & 3;
            s_basix[tid] = (n * 36 + oy * 6 + ox) * 256;
        }
    }
    __syncthreads();

    const __half *Ah, *Al, *Bp;
    if (PHASE == 1) { Ah = g_xh;        Al = g_xl;        Bp = g_w1[head]; }
    else            { Ah = g_m1h[head]; Al = g_m1l[head]; Bp = g_w2[head]; }

    auto prefetch = [&](int c) {
        const int kpos = c / CPK;
        const int coff = (c - kpos * CPK) * 64;
        const int ky = kpos / 3, kx = kpos - ky * 3;
        const int kadd = (PHASE == 1) ? ((ky * 8 + kx) * 512 + coff)
                                      : ((ky * 6 + kx) * 256 + coff);
        const int bko = kpos * KCIN + coff;
        const uint32_t stg = sbase + (c % 3) * STAGE_BYTES;
#pragma unroll
        for (int i = 0; i < 4; ++i) {                      // A: 128 rows x 128B, hi+lo
            int idx = tid + i * 256;
            int r = idx >> 3, seg = idx & 7;
            size_t e = (size_t)s_basix[r] + kadd + seg * 8;
            uint32_t off = (uint32_t)(r * 128 + seg * 16);
            uint32_t sw = off ^ ((uint32_t)(r & 7) << 4);
            cpa16(stg + sw,         Ah + e);
            cpa16(stg + 16384 + sw, Al + e);
        }
#pragma unroll
        for (int i = 0; i < 8; ++i) {                      // B: 256 rows x 128B
            int idx = tid + i * 256;
            int r = idx >> 3, seg = idx & 7;
            size_t e = (size_t)r * KTOT + bko + seg * 8;
            uint32_t off = (uint32_t)(r * 128 + seg * 16);
            uint32_t sw = off ^ ((uint32_t)(r & 7) << 4);
            cpa16(stg + 32768 + sw, Bp + e);
        }
        CP_COMMIT();
    };

    float acc[4][8][4];
#pragma unroll
    for (int mt = 0; mt < 4; ++mt)
#pragma unroll
        for (int nt = 0; nt < 8; ++nt)
#pragma unroll
            for (int q = 0; q < 4; ++q) acc[mt][nt][q] = 0.f;

    prefetch(0);
    prefetch(1);
    prefetch(2);

    const uint32_t lrow = lane & 15;
    const uint32_t lhi  = (uint32_t)(lane >> 4) << 4;

#pragma unroll 1
    for (int c = 0; c < CHUNKS; ++c) {
        const int rem = CHUNKS - c;
        if (rem >= 3) CP_WAIT2(); else if (rem == 2) CP_WAIT1(); else CP_WAIT0();
        __syncthreads();
        const uint32_t stg = sbase + (c % 3) * STAGE_BYTES;

#pragma unroll
        for (int ks = 0; ks < 4; ++ks) {
            uint32_t ah[4][4], bh[4][4], al[4][4];
#pragma unroll
            for (int mt = 0; mt < 4; ++mt) {
                uint32_t row = (uint32_t)(wm + mt * 16) + lrow;
                uint32_t off = row * 128 + (uint32_t)ks * 32 + lhi;
                ldm4(ah[mt], stg + (off ^ ((row & 7) << 4)));
            }
#pragma unroll
            for (int nt2 = 0; nt2 < 4; ++nt2) {
                uint32_t row = (uint32_t)(wn + nt2 * 16) + lrow;
                uint32_t off = row * 128 + (uint32_t)ks * 32 + lhi;
                ldm4(bh[nt2], stg + 32768 + (off ^ ((row & 7) << 4)));
            }
            // pass 1: Ah * B
#pragma unroll
            for (int mt = 0; mt < 4; ++mt)
#pragma unroll
                for (int nt = 0; nt < 8; ++nt)
                    mma16816(acc[mt][nt], ah[mt], bh[nt >> 1][nt & 1], bh[nt >> 1][(nt & 1) + 2]);
#pragma unroll
            for (int mt = 0; mt < 4; ++mt) {
                uint32_t row = (uint32_t)(wm + mt * 16) + lrow;
                uint32_t off = row * 128 + (uint32_t)ks * 32 + lhi;
                ldm4(al[mt], stg + 16384 + (off ^ ((row & 7) << 4)));
            }
            // pass 2: Al * B
#pragma unroll
            for (int mt = 0; mt < 4; ++mt)
#pragma unroll
                for (int nt = 0; nt < 8; ++nt)
                    mma16816(acc[mt][nt], al[mt], bh[nt >> 1][nt & 1], bh[nt >> 1][(nt & 1) + 2]);
        }

        __syncthreads();
        if (c + 3 < CHUNKS) prefetch(c + 3);
    }

    // ---- epilogue: frags -> smem -> (bias, relu) -> global ----
    float* epi = (float*)dsm;
    __syncthreads();
#pragma unroll
    for (int mt = 0; mt < 4; ++mt)
#pragma unroll
        for (int nt = 0; nt < 8; ++nt) {
            int r0 = wm + mt * 16 + (lane >> 2);
            int c0 = wn + nt * 8 + (lane & 3) * 2;
            *(float2*)&epi[r0 * EPI_PITCH + c0]       = make_float2(acc[mt][nt][0], acc[mt][nt][1]);
            *(float2*)&epi[(r0 + 8) * EPI_PITCH + c0] = make_float2(acc[mt][nt][2], acc[mt][nt][3]);
        }
    __syncthreads();

    if (PHASE == 1) {
        size_t mb = (size_t)tile * 128;
        const float b = bias[tid];
#pragma unroll 1
        for (int i = 0; i < 128; ++i) {
            float v = fmaxf(epi[i * EPI_PITCH + tid] + b, 0.f);
            __half h = __float2half_rn(v);
            __half l = __float2half_rn(v - __half2float(h));
            size_t o = (mb + i) * 256 + tid;
            g_m1h[head][o] = h;
            g_m1l[head][o] = l;
        }
    } else {
        float* outp = g_qkv[head] + (size_t)tile * 8 * 4096;
#pragma unroll 1
        for (int i = 0; i < 128; ++i) {
            int idx = tid + i * 256;
            int nl = idx >> 12, f = idx & 4095;
            int cout = f >> 4, p = f & 15;
            outp[idx] = fmaxf(epi[(nl * 16 + p) * EPI_PITCH + cout] + bias[cout], 0.f);
        }
    }
}

// ---------------- tiled block-diagonal attention ----------------------------------
// one block per 8 consecutive queries; union key segment is contiguous (sorted ids).
#define SMEM_ATT ((32768 + 16384 + 2048) * 4)

__global__ __launch_bounds__(256, 1)
void k_attn(const int* __restrict__ gid32, float* __restrict__ out) {
    extern __shared__ __align__(16) float asm_[];
    float* qsm  = asm_;                       // 8 x 4096
    float* srow = asm_ + 32768;               // 8 x 2048 (scores -> probs)
    int*   sgid = (int*)(asm_ + 32768 + 16384);

    __shared__ int s_jlo, s_jhi, s_rowg[8];
    __shared__ float s_red[8];

    const int qbase = blockIdx.x * 8;
    const int tid = threadIdx.x, warp = tid >> 5, lane = tid & 31;
    const int st = g_stride;

    if (tid == 0) {
        int g0 = gid32[qbase * st];
        int a = 0, b = NE;
        while (a < b) { int m = (a + b) >> 1; if (gid32[m * st] < g0) a = m + 1; else b = m; }
        s_jlo = a;
        int g7 = gid32[(qbase + 7) * st];
        a = 0; b = NE;
        while (a < b) { int m = (a + b) >> 1; if (gid32[m * st] <= g7) a = m + 1; else b = m; }
        s_jhi = a;
    }
    if (tid < 8) s_rowg[tid] = gid32[(qbase + tid) * st];
    __syncthreads();
    const int jlo = s_jlo, jhi = s_jhi, W = jhi - jlo;

    const float* qf = g_qkv[0];
    const float* kf = g_qkv[1];
    const float* vf = g_qkv[2];

    // load 8 q rows (8192 float4)
    {
        const float4* qg = (const float4*)(qf + (size_t)qbase * 4096);
        float4* q4 = (float4*)qsm;
#pragma unroll
        for (int i = 0; i < 32; ++i) q4[tid + i * 256] = qg[tid + i * 256];
    }
    for (int t = tid; t < W; t += 256) sgid[t] = gid32[(jlo + t) * st];
    __syncthreads();

    // ---- scores: 4 keys x 8 queries register blocking, one group of 4 per warp ----
    const float4* q4 = (const float4*)qsm;
    for (int j0 = jlo + warp * 4; j0 < jhi; j0 += 32) {
        float acc[4][8];
#pragma unroll
        for (int jj = 0; jj < 4; ++jj)
#pragma unroll
            for (int r = 0; r < 8; ++r) acc[jj][r] = 0.f;

        const float4* kp[4];
#pragma unroll
        for (int jj = 0; jj < 4; ++jj) {
            int jc = j0 + jj; if (jc >= jhi) jc = jhi - 1;
            kp[jj] = (const float4*)(kf + (size_t)jc * 4096);
        }
#pragma unroll 2
        for (int t = lane; t < 1024; t += 32) {
            float4 kv[4];
#pragma unroll
            for (int jj = 0; jj < 4; ++jj) kv[jj] = kp[jj][t];
#pragma unroll
            for (int r = 0; r < 8; ++r) {
                float4 qv = q4[r * 1024 + t];
#pragma unroll
                for (int jj = 0; jj < 4; ++jj) {
                    acc[jj][r] = fmaf(kv[jj].x, qv.x, acc[jj][r]);
                    acc[jj][r] = fmaf(kv[jj].y, qv.y, acc[jj][r]);
                    acc[jj][r] = fmaf(kv[jj].z, qv.z, acc[jj][r]);
                    acc[jj][r] = fmaf(kv[jj].w, qv.w, acc[jj][r]);
                }
            }
        }
#pragma unroll
        for (int jj = 0; jj < 4; ++jj)
#pragma unroll
            for (int r = 0; r < 8; ++r) {
                float v = acc[jj][r];
#pragma unroll
                for (int o = 16; o; o >>= 1) v += __shfl_xor_sync(0xffffffffu, v, o);
                if (lane == 0 && j0 + jj < jhi)
                    srow[r * 2048 + (j0 + jj - jlo)] = v * SCALE;
            }
    }
    __syncthreads();

    // ---- masked softmax: warp w owns query row w ----
    if (warp < 8) {
        const int r = warp;
        const int gr = s_rowg[r];
        float* sr = srow + r * 2048;
        float m = -INFINITY;
        for (int t = lane; t < W; t += 32)
            if (sgid[t] == gr) m = fmaxf(m, sr[t]);
#pragma unroll
        for (int o = 16; o; o >>= 1) m = fmaxf(m, __shfl_xor_sync(0xffffffffu, m, o));
        float ssum = 0.f;
        for (int t = lane; t < W; t += 32) {
            float e = (sgid[t] == gr) ? __expf(sr[t] - m) : 0.f;
            sr[t] = e;
            ssum += e;
        }
#pragma unroll
        for (int o = 16; o; o >>= 1) ssum += __shfl_xor_sync(0xffffffffu, ssum, o);
        float inv = 1.f / ssum;
        for (int t = lane; t < W; t += 32) sr[t] *= inv;
    }
    __syncthreads();

    // ---- AV: out tile 8 x 4096, two feature halves (64 accum regs each) ----
#pragma unroll 1
    for (int hh = 0; hh < 2; ++hh) {
        float4 a0[8], a1[8];
#pragma unroll
        for (int r = 0; r < 8; ++r) {
            a0[r] = make_float4(0.f, 0.f, 0.f, 0.f);
            a1[r] = a0[r];
        }
        const int f4 = hh * 512 + tid * 2;                 // float4 index within row
#pragma unroll 1
        for (int jt = 0; jt < W; ++jt) {
            const float4* vp = (const float4*)(vf + (size_t)(jlo + jt) * 4096) + f4;
            float4 v0 = vp[0], v1 = vp[1];
#pragma unroll
            for (int r = 0; r < 8; ++r) {
                float p = srow[r * 2048 + jt];
                a0[r].x = fmaf(p, v0.x, a0[r].x); a0[r].y = fmaf(p, v0.y, a0[r].y);
                a0[r].z = fmaf(p, v0.z, a0[r].z); a0[r].w = fmaf(p, v0.w, a0[r].w);
                a1[r].x = fmaf(p, v1.x, a1[r].x); a1[r].y = fmaf(p, v1.y, a1[r].y);
                a1[r].z = fmaf(p, v1.z, a1[r].z); a1[r].w = fmaf(p, v1.w, a1[r].w);
            }
        }
#pragma unroll
        for (int r = 0; r < 8; ++r) {
            float4* op = (float4*)(out + (size_t)(qbase + r) * 4096) + f4;
            op[0] = a0[r];
            op[1] = a1[r];
        }
    }
}

// ---------------- launch ----------------------------------------------------------
extern "C" void kernel_launch(void* const* d_in, const int* in_sizes, int n_in,
                              void* d_out, int out_size) {
    const float* x     = (const float*)d_in[0];
    const int*   gid32 = (const int*)d_in[1];

    const float* w1[3] = {(const float*)d_in[2], (const float*)d_in[6],  (const float*)d_in[10]};
    const float* b1[3] = {(const float*)d_in[3], (const float*)d_in[7],  (const float*)d_in[11]};
    const float* w2[3] = {(const float*)d_in[4], (const float*)d_in[8],  (const float*)d_in[12]};
    const float* b2[3] = {(const float*)d_in[5], (const float*)d_in[9],  (const float*)d_in[13]};

    cudaFuncSetAttribute(k_gemm<1>, cudaFuncAttributeMaxDynamicSharedMemorySize, SMEM_DYN);
    cudaFuncSetAttribute(k_gemm<2>, cudaFuncAttributeMaxDynamicSharedMemorySize, SMEM_DYN);
    cudaFuncSetAttribute(k_attn,    cudaFuncAttributeMaxDynamicSharedMemorySize, SMEM_ATT);

    k_detect<<<1, 256>>>(gid32);
    k_prep_x<<<dim3(2048, 8), 256>>>(x);
    k_prep_w1<<<dim3(256, 3), 256>>>(w1[0], w1[1], w1[2]);
    k_prep_w2<<<dim3(256, 3), 256>>>(w2[0], w2[1], w2[2]);

    k_gemm<1><<<dim3(576, 3), 256, SMEM_DYN>>>(b1[0], b1[1], b1[2]);
    k_gemm<2><<<dim3(256, 3), 256, SMEM_DYN>>>(b2[0], b2[1], b2[2]);

    k_attn<<<256, 256, SMEM_ATT>>>(gid32, (float*)d_out);
}

// round 8
// speedup vs baseline: 3.7236x; 1.0918x over previous
#include <cuda_runtime.h>
#include <cuda_fp16.h>
#include <math.h>
#include <stdint.h>

#define NE 2048
#define SCALE 0.04419417382415922f   /* 1/sqrt(2*256) */

// ---------------- device scratch (static globals; no allocation) ----------------
__device__ __align__(16) __half g_x16[(size_t)NE * 64 * 512];  // x NHWC fp16
__device__ __align__(16) __half g_w1[3][4608 * 256];           // conv1 W [cout][k] fp16
__device__ __align__(16) __half g_w2[3][2304 * 256];           // conv2 W fp16
__device__ __align__(16) __half g_m1[3][(size_t)73728 * 256];  // conv1 out fp16
__device__ float g_qkv[3][(size_t)NE * 4096];                  // conv2 out fp32
__device__ int   g_stride;

// ---------------- PTX helpers -----------------------------------------------------
__device__ __forceinline__ uint32_t smem_u32(const void* p) {
    uint32_t a;
    asm("{ .reg .u64 t; cvta.to.shared.u64 t, %1; cvt.u32.u64 %0, t; }" : "=r"(a) : "l"(p));
    return a;
}
__device__ __forceinline__ void cpa16(uint32_t dst, const void* src) {
    asm volatile("cp.async.cg.shared.global [%0], [%1], 16;" :: "r"(dst), "l"(src) : "memory");
}
#define CP_COMMIT() asm volatile("cp.async.commit_group;" ::: "memory")
#define CP_WAIT2()  asm volatile("cp.async.wait_group 2;" ::: "memory")
#define CP_WAIT1()  asm volatile("cp.async.wait_group 1;" ::: "memory")
#define CP_WAIT0()  asm volatile("cp.async.wait_group 0;" ::: "memory")

__device__ __forceinline__ void ldm4(uint32_t* r, uint32_t addr) {
    asm volatile("ldmatrix.sync.aligned.m8n8.x4.shared.b16 {%0,%1,%2,%3}, [%4];"
        : "=r"(r[0]), "=r"(r[1]), "=r"(r[2]), "=r"(r[3]) : "r"(addr));
}
__device__ __forceinline__ void mma16816(float* d, const uint32_t* a, uint32_t b0, uint32_t b1) {
    asm volatile("mma.sync.aligned.m16n8k16.row.col.f32.f16.f16.f32 "
        "{%0,%1,%2,%3}, {%4,%5,%6,%7}, {%8,%9}, {%0,%1,%2,%3};"
        : "+f"(d[0]), "+f"(d[1]), "+f"(d[2]), "+f"(d[3])
        : "r"(a[0]), "r"(a[1]), "r"(a[2]), "r"(a[3]), "r"(b0), "r"(b1));
}

// ---------------- graph-id dtype detection ---------------------------------------
__global__ void k_detect(const int* __restrict__ gid32) {
    __shared__ int bad;
    if (threadIdx.x == 0) bad = 0;
    __syncthreads();
    for (int i = threadIdx.x; i < NE - 1; i += blockDim.x)
        if (gid32[i] > gid32[i + 1]) bad = 1;
    __syncthreads();
    if (threadIdx.x == 0) g_stride = bad ? 2 : 1;
}

// ---------------- prep: x NCHW fp32 -> NHWC fp16 ----------------------------------
__global__ void k_prep_x(const float* __restrict__ x) {      // grid (2048, 8), 256 thr
    __shared__ float tile[64][65];
    const int n = blockIdx.x, cc = blockIdx.y;
#pragma unroll
    for (int i = 0; i < 16; ++i) {
        int t = threadIdx.x + i * 256;
        int ci = t >> 6, yx = t & 63;
        tile[ci][yx] = x[(size_t)n * 32768 + (cc * 64 + ci) * 64 + yx];
    }
    __syncthreads();
#pragma unroll
    for (int i = 0; i < 16; ++i) {
        int t = threadIdx.x + i * 256;
        int yx = t >> 6, ci = t & 63;
        size_t o = ((size_t)n * 64 + yx) * 512 + cc * 64 + ci;
        g_x16[o] = __float2half_rn(tile[ci][yx]);
    }
}

// ---------------- prep: weights -> [cout][kpos*Cin + cin] fp16 --------------------
__global__ void k_prep_w1(const float* __restrict__ wq, const float* __restrict__ wk,
                          const float* __restrict__ wv) {    // grid (256, 3)
    const int cout = blockIdx.x, h = blockIdx.y;
    const float* w = (h == 0) ? wq : (h == 1) ? wk : wv;
#pragma unroll
    for (int i = 0; i < 18; ++i) {
        int k = threadIdx.x + i * 256;                       // 0..4607
        int kpos = k >> 9, cin = k & 511;
        g_w1[h][cout * 4608 + k] = __float2half_rn(w[cout * 4608 + cin * 9 + kpos]);
    }
}

__global__ void k_prep_w2(const float* __restrict__ wq, const float* __restrict__ wk,
                          const float* __restrict__ wv) {    // grid (256, 3)
    const int cout = blockIdx.x, h = blockIdx.y;
    const float* w = (h == 0) ? wq : (h == 1) ? wk : wv;
#pragma unroll
    for (int i = 0; i < 9; ++i) {
        int k = threadIdx.x + i * 256;                       // 0..2303
        int kpos = k >> 8, cin = k & 255;
        g_w2[h][cout * 2304 + k] = __float2half_rn(w[cout * 2304 + cin * 9 + kpos]);
    }
}

// ---------------- HMMA GEMM: conv1 (PHASE 1) / conv2 (PHASE 2) --------------------
// CTA: M=128 x N=256, K chunks of 64. 8 warps of 64x64. 3-stage cp.async pipeline.
// Stage: A @0 (16K) | B @16K (32K) = 48K. Single fp16 pass.
#define STAGE_BYTES 49152
#define SMEM_DYN    (3 * STAGE_BYTES)
#define EPI_PITCH   260

template <int PHASE>
__global__ void __launch_bounds__(256, 1)
k_gemm(const float* __restrict__ bq, const float* __restrict__ bk,
       const float* __restrict__ bv) {
    extern __shared__ __align__(1024) char dsm[];
    const uint32_t sbase = smem_u32(dsm);

    const int tile = blockIdx.x, head = blockIdx.y;
    const int tid  = threadIdx.x, wid = tid >> 5, lane = tid & 31;
    const int wm   = (wid >> 2) * 64;        // warp m offset
    const int wn   = (wid & 3) * 64;         // warp n offset
    const float* bias = (head == 0) ? bq : (head == 1) ? bk : bv;

    __shared__ int s_basix[128];

    constexpr int CHUNKS = (PHASE == 1) ? 72 : 36;
    constexpr int CPK    = (PHASE == 1) ? 8 : 4;
    constexpr int KCIN   = (PHASE == 1) ? 512 : 256;
    constexpr int KTOT   = (PHASE == 1) ? 4608 : 2304;

    if (tid < 128) {
        int m = tile * 128 + tid;
        if (PHASE == 1) {
            int n = m / 36, p = m - n * 36, oy = p / 6, ox = p - oy * 6;
            s_basix[tid] = (n * 64 + oy * 8 + ox) * 512;
        } else {
            int n = m >> 4, p = m & 15, oy = p >> 2, ox = p & 3;
            s_basix[tid] = (n * 36 + oy * 6 + ox) * 256;
        }
    }
    __syncthreads();

    const __half *Ap, *Bp;
    if (PHASE == 1) { Ap = g_x16;      Bp = g_w1[head]; }
    else            { Ap = g_m1[head]; Bp = g_w2[head]; }

    auto prefetch = [&](int c) {
        const int kpos = c / CPK;
        const int coff = (c - kpos * CPK) * 64;
        const int ky = kpos / 3, kx = kpos - ky * 3;
        const int kadd = (PHASE == 1) ? ((ky * 8 + kx) * 512 + coff)
                                      : ((ky * 6 + kx) * 256 + coff);
        const int bko = kpos * KCIN + coff;
        const uint32_t stg = sbase + (c % 3) * STAGE_BYTES;
#pragma unroll
        for (int i = 0; i < 4; ++i) {                      // A: 128 rows x 128B
            int idx = tid + i * 256;
            int r = idx >> 3, seg = idx & 7;
            size_t e = (size_t)s_basix[r] + kadd + seg * 8;
            uint32_t off = (uint32_t)(r * 128 + seg * 16);
            uint32_t sw = off ^ ((uint32_t)(r & 7) << 4);
            cpa16(stg + sw, Ap + e);
        }
#pragma unroll
        for (int i = 0; i < 8; ++i) {                      // B: 256 rows x 128B
            int idx = tid + i * 256;
            int r = idx >> 3, seg = idx & 7;
            size_t e = (size_t)r * KTOT + bko + seg * 8;
            uint32_t off = (uint32_t)(r * 128 + seg * 16);
            uint32_t sw = off ^ ((uint32_t)(r & 7) << 4);
            cpa16(stg + 16384 + sw, Bp + e);
        }
        CP_COMMIT();
    };

    float acc[4][8][4];
#pragma unroll
    for (int mt = 0; mt < 4; ++mt)
#pragma unroll
        for (int nt = 0; nt < 8; ++nt)
#pragma unroll
            for (int q = 0; q < 4; ++q) acc[mt][nt][q] = 0.f;

    prefetch(0);
    prefetch(1);
    prefetch(2);

    const uint32_t lrow = lane & 15;
    const uint32_t lhi  = (uint32_t)(lane >> 4) << 4;

#pragma unroll 1
    for (int c = 0; c < CHUNKS; ++c) {
        const int rem = CHUNKS - c;
        if (rem >= 3) CP_WAIT2(); else if (rem == 2) CP_WAIT1(); else CP_WAIT0();
        __syncthreads();
        const uint32_t stg = sbase + (c % 3) * STAGE_BYTES;

#pragma unroll
        for (int ks = 0; ks < 4; ++ks) {
            uint32_t ah[4][4], bh[4][4];
#pragma unroll
            for (int mt = 0; mt < 4; ++mt) {
                uint32_t row = (uint32_t)(wm + mt * 16) + lrow;
                uint32_t off = row * 128 + (uint32_t)ks * 32 + lhi;
                ldm4(ah[mt], stg + (off ^ ((row & 7) << 4)));
            }
#pragma unroll
            for (int nt2 = 0; nt2 < 4; ++nt2) {
                uint32_t row = (uint32_t)(wn + nt2 * 16) + lrow;
                uint32_t off = row * 128 + (uint32_t)ks * 32 + lhi;
                ldm4(bh[nt2], stg + 16384 + (off ^ ((row & 7) << 4)));
            }
#pragma unroll
            for (int mt = 0; mt < 4; ++mt)
#pragma unroll
                for (int nt = 0; nt < 8; ++nt)
                    mma16816(acc[mt][nt], ah[mt], bh[nt >> 1][nt & 1], bh[nt >> 1][(nt & 1) + 2]);
        }

        __syncthreads();
        if (c + 3 < CHUNKS) prefetch(c + 3);
    }

    // ---- epilogue: frags -> smem -> (bias, relu) -> global ----
    float* epi = (float*)dsm;
    __syncthreads();
#pragma unroll
    for (int mt = 0; mt < 4; ++mt)
#pragma unroll
        for (int nt = 0; nt < 8; ++nt) {
            int r0 = wm + mt * 16 + (lane >> 2);
            int c0 = wn + nt * 8 + (lane & 3) * 2;
            *(float2*)&epi[r0 * EPI_PITCH + c0]       = make_float2(acc[mt][nt][0], acc[mt][nt][1]);
            *(float2*)&epi[(r0 + 8) * EPI_PITCH + c0] = make_float2(acc[mt][nt][2], acc[mt][nt][3]);
        }
    __syncthreads();

    if (PHASE == 1) {
        size_t mb = (size_t)tile * 128;
        const float b = bias[tid];
#pragma unroll 1
        for (int i = 0; i < 128; ++i) {
            float v = fmaxf(epi[i * EPI_PITCH + tid] + b, 0.f);
            g_m1[head][(mb + i) * 256 + tid] = __float2half_rn(v);
        }
    } else {
        float* outp = g_qkv[head] + (size_t)tile * 8 * 4096;
#pragma unroll 1
        for (int i = 0; i < 128; ++i) {
            int idx = tid + i * 256;
            int nl = idx >> 12, f = idx & 4095;
            int cout = f >> 4, p = f & 15;
            outp[idx] = fmaxf(epi[(nl * 16 + p) * EPI_PITCH + cout] + bias[cout], 0.f);
        }
    }
}

// ---------------- tiled block-diagonal attention ----------------------------------
// one block per 8 consecutive queries; union key segment is contiguous (sorted ids).
#define SMEM_ATT ((32768 + 16384 + 2048) * 4)

__global__ __launch_bounds__(256, 1)
void k_attn(const int* __restrict__ gid32, float* __restrict__ out) {
    extern __shared__ __align__(16) float asm_[];
    float* qsm  = asm_;                       // 8 x 4096
    float* srow = asm_ + 32768;               // 8 x 2048 (scores -> probs)
    int*   sgid = (int*)(asm_ + 32768 + 16384);

    __shared__ int s_jlo, s_jhi, s_rowg[8];

    const int qbase = blockIdx.x * 8;
    const int tid = threadIdx.x, warp = tid >> 5, lane = tid & 31;
    const int st = g_stride;

    if (tid == 0) {
        int g0 = gid32[qbase * st];
        int a = 0, b = NE;
        while (a < b) { int m = (a + b) >> 1; if (gid32[m * st] < g0) a = m + 1; else b = m; }
        s_jlo = a;
        int g7 = gid32[(qbase + 7) * st];
        a = 0; b = NE;
        while (a < b) { int m = (a + b) >> 1; if (gid32[m * st] <= g7) a = m + 1; else b = m; }
        s_jhi = a;
    }
    if (tid < 8) s_rowg[tid] = gid32[(qbase + tid) * st];
    __syncthreads();
    const int jlo = s_jlo, jhi = s_jhi, W = jhi - jlo;

    const float* qf = g_qkv[0];
    const float* kf = g_qkv[1];
    const float* vf = g_qkv[2];

    // load 8 q rows (8192 float4)
    {
        const float4* qg = (const float4*)(qf + (size_t)qbase * 4096);
        float4* q4 = (float4*)qsm;
#pragma unroll
        for (int i = 0; i < 32; ++i) q4[tid + i * 256] = qg[tid + i * 256];
    }
    for (int t = tid; t < W; t += 256) sgid[t] = gid32[(jlo + t) * st];
    __syncthreads();

    // ---- scores: 4 keys x 8 queries register blocking, one group of 4 per warp ----
    const float4* q4 = (const float4*)qsm;
    for (int j0 = jlo + warp * 4; j0 < jhi; j0 += 32) {
        float acc[4][8];
#pragma unroll
        for (int jj = 0; jj < 4; ++jj)
#pragma unroll
            for (int r = 0; r < 8; ++r) acc[jj][r] = 0.f;

        const float4* kp[4];
#pragma unroll
        for (int jj = 0; jj < 4; ++jj) {
            int jc = j0 + jj; if (jc >= jhi) jc = jhi - 1;
            kp[jj] = (const float4*)(kf + (size_t)jc * 4096);
        }
#pragma unroll 2
        for (int t = lane; t < 1024; t += 32) {
            float4 kv[4];
#pragma unroll
            for (int jj = 0; jj < 4; ++jj) kv[jj] = kp[jj][t];
#pragma unroll
            for (int r = 0; r < 8; ++r) {
                float4 qv = q4[r * 1024 + t];
#pragma unroll
                for (int jj = 0; jj < 4; ++jj) {
                    acc[jj][r] = fmaf(kv[jj].x, qv.x, acc[jj][r]);
                    acc[jj][r] = fmaf(kv[jj].y, qv.y, acc[jj][r]);
                    acc[jj][r] = fmaf(kv[jj].z, qv.z, acc[jj][r]);
                    acc[jj][r] = fmaf(kv[jj].w, qv.w, acc[jj][r]);
                }
            }
        }
#pragma unroll
        for (int jj = 0; jj < 4; ++jj)
#pragma unroll
            for (int r = 0; r < 8; ++r) {
                float v = acc[jj][r];
#pragma unroll
                for (int o = 16; o; o >>= 1) v += __shfl_xor_sync(0xffffffffu, v, o);
                if (lane == 0 && j0 + jj < jhi)
                    srow[r * 2048 + (j0 + jj - jlo)] = v * SCALE;
            }
    }
    __syncthreads();

    // ---- masked softmax: warp w owns query row w ----
    if (warp < 8) {
        const int r = warp;
        const int gr = s_rowg[r];
        float* sr = srow + r * 2048;
        float m = -INFINITY;
        for (int t = lane; t < W; t += 32)
            if (sgid[t] == gr) m = fmaxf(m, sr[t]);
#pragma unroll
        for (int o = 16; o; o >>= 1) m = fmaxf(m, __shfl_xor_sync(0xffffffffu, m, o));
        float ssum = 0.f;
        for (int t = lane; t < W; t += 32) {
            float e = (sgid[t] == gr) ? __expf(sr[t] - m) : 0.f;
            sr[t] = e;
            ssum += e;
        }
#pragma unroll
        for (int o = 16; o; o >>= 1) ssum += __shfl_xor_sync(0xffffffffu, ssum, o);
        float inv = 1.f / ssum;
        for (int t = lane; t < W; t += 32) sr[t] *= inv;
    }
    __syncthreads();

    // ---- AV: out tile 8 x 4096, two feature halves (64 accum regs each) ----
#pragma unroll 1
    for (int hh = 0; hh < 2; ++hh) {
        float4 a0[8], a1[8];
#pragma unroll
        for (int r = 0; r < 8; ++r) {
            a0[r] = make_float4(0.f, 0.f, 0.f, 0.f);
            a1[r] = a0[r];
        }
        const int f4 = hh * 512 + tid * 2;                 // float4 index within row
#pragma unroll 1
        for (int jt = 0; jt < W; ++jt) {
            const float4* vp = (const float4*)(vf + (size_t)(jlo + jt) * 4096) + f4;
            float4 v0 = vp[0], v1 = vp[1];
#pragma unroll
            for (int r = 0; r < 8; ++r) {
                float p = srow[r * 2048 + jt];
                a0[r].x = fmaf(p, v0.x, a0[r].x); a0[r].y = fmaf(p, v0.y, a0[r].y);
                a0[r].z = fmaf(p, v0.z, a0[r].z); a0[r].w = fmaf(p, v0.w, a0[r].w);
                a1[r].x = fmaf(p, v1.x, a1[r].x); a1[r].y = fmaf(p, v1.y, a1[r].y);
                a1[r].z = fmaf(p, v1.z, a1[r].z); a1[r].w = fmaf(p, v1.w, a1[r].w);
            }
        }
#pragma unroll
        for (int r = 0; r < 8; ++r) {
            float4* op = (float4*)(out + (size_t)(qbase + r) * 4096) + f4;
            op[0] = a0[r];
            op[1] = a1[r];
        }
    }
}

// ---------------- launch ----------------------------------------------------------
extern "C" void kernel_launch(void* const* d_in, const int* in_sizes, int n_in,
                              void* d_out, int out_size) {
    const float* x     = (const float*)d_in[0];
    const int*   gid32 = (const int*)d_in[1];

    const float* w1[3] = {(const float*)d_in[2], (const float*)d_in[6],  (const float*)d_in[10]};
    const float* b1[3] = {(const float*)d_in[3], (const float*)d_in[7],  (const float*)d_in[11]};
    const float* w2[3] = {(const float*)d_in[4], (const float*)d_in[8],  (const float*)d_in[12]};
    const float* b2[3] = {(const float*)d_in[5], (const float*)d_in[9],  (const float*)d_in[13]};

    cudaFuncSetAttribute(k_gemm<1>, cudaFuncAttributeMaxDynamicSharedMemorySize, SMEM_DYN);
    cudaFuncSetAttribute(k_gemm<2>, cudaFuncAttributeMaxDynamicSharedMemorySize, SMEM_DYN);
    cudaFuncSetAttribute(k_attn,    cudaFuncAttributeMaxDynamicSharedMemorySize, SMEM_ATT);

    k_detect<<<1, 256>>>(gid32);
    k_prep_x<<<dim3(2048, 8), 256>>>(x);
    k_prep_w1<<<dim3(256, 3), 256>>>(w1[0], w1[1], w1[2]);
    k_prep_w2<<<dim3(256, 3), 256>>>(w2[0], w2[1], w2[2]);

    k_gemm<1><<<dim3(576, 3), 256, SMEM_DYN>>>(b1[0], b1[1], b1[2]);
    k_gemm<2><<<dim3(256, 3), 256, SMEM_DYN>>>(b2[0], b2[1], b2[2]);

    k_attn<<<256, 256, SMEM_ATT>>>(gid32, (float*)d_out);
}